// round 11
// baseline (speedup 1.0000x reference)
#include <cuda_runtime.h>
#include <cstdint>
#include <math.h>

// Problem dims
#define B_DIM 128
#define S_DIM 1024
#define I_DIM 256
#define H_DIM 512
#define G4H   2048
#define O_DIM 10

// Recurrence partition: 128 persistent CTAs = 4 batch parts x 32 k parts
#define NCTA   128
#define PPARTS 4
#define QPARTS 32
#define GRP    32           // CTAs per barrier group (one batch part)
#define BP (B_DIM/PPARTS)   // 32 batch rows per CTA
#define KP (H_DIM/QPARTS)   // 16 h-columns per CTA

#define WS_PITCH 516        // 512 + 4 pad -> conflict-free tf32 fragment LDS
#define GS_PITCH 66         // float2-aligned, low-conflict gate scatter

// smem: W slice [64][516] u32 + h tile [32][516] u32 + gate slabs [4][32][66] f32
#define SMEM_LSTM_BYTES ((64*WS_PITCH + 32*WS_PITCH)*4 + 4*32*GS_PITCH*4)

// Scratch (device globals: the sanctioned no-alloc workaround)
__device__ float g_xp[(size_t)S_DIM * B_DIM * G4H];   // 1 GB: x_proj in [s][b][g]
__device__ float g_h[2][B_DIM * H_DIM];               // ping-pong h
__device__ unsigned long long g_bar4[64];             // 4 group barriers, 128B apart

__device__ __forceinline__ uint32_t f2tf(float x) {
    uint32_t r;
    asm("cvt.rna.tf32.f32 %0, %1;" : "=r"(r) : "f"(x));
    return r;
}

__device__ __forceinline__ void mma8(float& d0, float& d1, float& d2, float& d3,
                                     uint32_t a0, uint32_t a1, uint32_t a2, uint32_t a3,
                                     uint32_t b0, uint32_t b1) {
    asm volatile(
        "mma.sync.aligned.m16n8k8.row.col.f32.tf32.tf32.f32 "
        "{%0,%1,%2,%3},{%4,%5,%6,%7},{%8,%9},{%0,%1,%2,%3};"
        : "+f"(d0), "+f"(d1), "+f"(d2), "+f"(d3)
        : "r"(a0), "r"(a1), "r"(a2), "r"(a3), "r"(b0), "r"(b1));
}

// ============================================================================
// Phase 1: x_proj[s][b][g] = sum_i x[b][s][i] * W_ih[g][i] + b_ih[g] + b_hh[g]
// CTA tile: fixed batch b, M=128 contiguous s rows (sequential x reads),
// N=128 gate cols, K=256 in 8 chunks of 32.
// ============================================================================
__global__ __launch_bounds__(256) void xproj_kernel(
    const float* __restrict__ x, const float* __restrict__ Wih,
    const float* __restrict__ bih, const float* __restrict__ bhh) {
    __shared__ uint32_t As[128][36];
    __shared__ uint32_t Bs[128][36];

    const int b   = blockIdx.z;
    const int s0  = blockIdx.y * 128;
    const int n0  = blockIdx.x * 128;
    const int tid = threadIdx.x;
    const int warp = tid >> 5, lane = tid & 31;
    const int gid = lane >> 2, tq = lane & 3;
    const int mw = warp >> 1, nw = warp & 1;   // 4 M-warps x 2 N-warps

    float acc[2][8][4] = {};

    for (int kc = 0; kc < I_DIM; kc += 32) {
        __syncthreads();
#pragma unroll
        for (int j = 0; j < 4; j++) {
            int id = tid + 256 * j;          // 1024 float4 per tile
            int r  = id >> 3;                // row 0..127
            int c  = (id & 7) * 4;           // col 0..28
            float4 av = *reinterpret_cast<const float4*>(
                x + ((size_t)b * S_DIM + s0 + r) * I_DIM + kc + c);
            As[r][c]   = f2tf(av.x); As[r][c+1] = f2tf(av.y);
            As[r][c+2] = f2tf(av.z); As[r][c+3] = f2tf(av.w);
            float4 bv = *reinterpret_cast<const float4*>(
                Wih + (size_t)(n0 + r) * I_DIM + kc + c);
            Bs[r][c]   = f2tf(bv.x); Bs[r][c+1] = f2tf(bv.y);
            Bs[r][c+2] = f2tf(bv.z); Bs[r][c+3] = f2tf(bv.w);
        }
        __syncthreads();
#pragma unroll
        for (int ks = 0; ks < 32; ks += 8) {
            uint32_t a[2][4];
#pragma unroll
            for (int mt = 0; mt < 2; mt++) {
                int m0 = mw * 32 + mt * 16;
                a[mt][0] = As[m0 + gid][ks + tq];
                a[mt][1] = As[m0 + gid + 8][ks + tq];
                a[mt][2] = As[m0 + gid][ks + tq + 4];
                a[mt][3] = As[m0 + gid + 8][ks + tq + 4];
            }
#pragma unroll
            for (int nt = 0; nt < 8; nt++) {
                int nn = nw * 64 + nt * 8;
                uint32_t b0 = Bs[nn + gid][ks + tq];
                uint32_t b1 = Bs[nn + gid][ks + tq + 4];
                mma8(acc[0][nt][0], acc[0][nt][1], acc[0][nt][2], acc[0][nt][3],
                     a[0][0], a[0][1], a[0][2], a[0][3], b0, b1);
                mma8(acc[1][nt][0], acc[1][nt][1], acc[1][nt][2], acc[1][nt][3],
                     a[1][0], a[1][1], a[1][2], a[1][3], b0, b1);
            }
        }
    }

#pragma unroll
    for (int mt = 0; mt < 2; mt++) {
        int row = mw * 32 + mt * 16 + gid;       // s offset within block
#pragma unroll
        for (int nt = 0; nt < 8; nt++) {
            int col = n0 + nw * 64 + nt * 8 + tq * 2;
            float bs0 = bih[col]     + bhh[col];
            float bs1 = bih[col + 1] + bhh[col + 1];
            size_t r0 = ((size_t)(s0 + row) * B_DIM + b) * G4H + col;
            size_t r1 = ((size_t)(s0 + row + 8) * B_DIM + b) * G4H + col;
            g_xp[r0]     = acc[mt][nt][0] + bs0;
            g_xp[r0 + 1] = acc[mt][nt][1] + bs1;
            g_xp[r1]     = acc[mt][nt][2] + bs0;
            g_xp[r1 + 1] = acc[mt][nt][3] + bs1;
        }
    }
}

// ============================================================================
// Phase 2: persistent recurrence. CTA (p,q): batch rows [p*32,p*32+32),
// h-cols [q*16,q*16+16). Warp tiling: 8 warps = 4 k-parts x 2 n-halves,
// each warp mt=2 x nt=4 (16 LDS per 8 MMAs). Cross-k partials summed through
// 4 gs slabs. Group barrier over the 32 CTAs sharing a batch part.
// ============================================================================
__global__ __launch_bounds__(256, 1) void lstm_kernel(const float* __restrict__ Whh) {
    extern __shared__ uint32_t sm[];
    uint32_t* Ws = sm;                                   // [64][516]
    uint32_t* hs = sm + 64 * WS_PITCH;                   // [32][516]
    float*    gs = (float*)(sm + (64 + 32) * WS_PITCH);  // [4][32][66]

    const int tid  = threadIdx.x;
    const int warp = tid >> 5, lane = tid & 31;
    const int gid  = lane >> 2, tq = lane & 3;
    const int kp = warp & 3;         // k-part: K range [kp*128, kp*128+128)
    const int nh = warp >> 2;        // n-half: N cols [nh*32, nh*32+32)
    const int q = blockIdx.x & (QPARTS - 1);
    const int p = blockIdx.x >> 5;

    // Load resident W_hh slice (tf32 in smem). Row r (0..63): gate r/16, k-col q*16 + r%16.
#pragma unroll
    for (int it = 0; it < 32; it++) {
        int id = tid + 256 * it;           // 8192 float4
        int r  = id >> 7;                  // 0..63
        int c4 = (id & 127) * 4;
        int grow = (r >> 4) * H_DIM + q * KP + (r & 15);
        float4 v = *reinterpret_cast<const float4*>(Whh + (size_t)grow * H_DIM + c4);
        uint32_t* d = Ws + r * WS_PITCH + c4;
        d[0] = f2tf(v.x); d[1] = f2tf(v.y); d[2] = f2tf(v.z); d[3] = f2tf(v.w);
    }

    // Persistent c-state: thread owns (b,k) pairs tid and tid+256.
    float creg[2] = {0.f, 0.f};
    const int kk = tid & 15;

    // Prefetch x_proj gate values for t=0.
    float xv[2][4];
    {
        const float* xps = g_xp + ((size_t)p * BP) * G4H;
#pragma unroll
        for (int r2 = 0; r2 < 2; r2++) {
            int bl = (tid + r2 * 256) >> 4;
#pragma unroll
            for (int g = 0; g < 4; g++)
                xv[r2][g] = xps[(size_t)bl * G4H + g * 512 + q * KP + kk];
        }
    }

    for (int t = 0; t < S_DIM; t++) {
        if (t > 0) {  // stage h_{t-1} (full H for our batch rows) into smem as tf32
            const float* hp = g_h[(t + 1) & 1] + (size_t)p * BP * H_DIM;
#pragma unroll
            for (int j = 0; j < 16; j++) {
                int id = tid + 256 * j;       // 4096 float4
                int r  = id >> 7;             // 0..31
                int c4 = (id & 127) * 4;
                float4 v = *reinterpret_cast<const float4*>(hp + (size_t)r * H_DIM + c4);
                uint32_t* d = hs + r * WS_PITCH + c4;
                d[0] = f2tf(v.x); d[1] = f2tf(v.y); d[2] = f2tf(v.z); d[3] = f2tf(v.w);
            }
        }
        __syncthreads();

        float acc[2][4][4] = {};
        if (t > 0) {
#pragma unroll 4
            for (int ks = 0; ks < 16; ks++) {
                int k0 = kp * 128 + ks * 8;
                uint32_t a[2][4];
#pragma unroll
                for (int mt = 0; mt < 2; mt++) {
                    int m0 = mt * 16;
                    a[mt][0] = hs[(m0 + gid) * WS_PITCH + k0 + tq];
                    a[mt][1] = hs[(m0 + gid + 8) * WS_PITCH + k0 + tq];
                    a[mt][2] = hs[(m0 + gid) * WS_PITCH + k0 + tq + 4];
                    a[mt][3] = hs[(m0 + gid + 8) * WS_PITCH + k0 + tq + 4];
                }
#pragma unroll
                for (int nt = 0; nt < 4; nt++) {
                    int nn = nh * 32 + nt * 8;
                    uint32_t b0 = Ws[(nn + gid) * WS_PITCH + k0 + tq];
                    uint32_t b1 = Ws[(nn + gid) * WS_PITCH + k0 + tq + 4];
                    mma8(acc[0][nt][0], acc[0][nt][1], acc[0][nt][2], acc[0][nt][3],
                         a[0][0], a[0][1], a[0][2], a[0][3], b0, b1);
                    mma8(acc[1][nt][0], acc[1][nt][1], acc[1][nt][2], acc[1][nt][3],
                         a[1][0], a[1][1], a[1][2], a[1][3], b0, b1);
                }
            }
        }

        // Scatter k-part partials into slab kp (float2 stores, 8B aligned).
        {
            float* gsp = gs + kp * 32 * GS_PITCH;
#pragma unroll
            for (int mt = 0; mt < 2; mt++) {
                int row = mt * 16 + gid;
#pragma unroll
                for (int nt = 0; nt < 4; nt++) {
                    int col = nh * 32 + nt * 8 + tq * 2;
                    *reinterpret_cast<float2*>(gsp + row * GS_PITCH + col) =
                        make_float2(acc[mt][nt][0], acc[mt][nt][1]);
                    *reinterpret_cast<float2*>(gsp + (row + 8) * GS_PITCH + col) =
                        make_float2(acc[mt][nt][2], acc[mt][nt][3]);
                }
            }
        }
        __syncthreads();

        // Elementwise: sum 4 k-slabs + x_proj, gate math, c update, h write.
        float* hdst = g_h[t & 1];
#pragma unroll
        for (int r2 = 0; r2 < 2; r2++) {
            int bl = (tid + r2 * 256) >> 4;
            float yi = xv[r2][0], yf = xv[r2][1], yg = xv[r2][2], yo = xv[r2][3];
#pragma unroll
            for (int s4 = 0; s4 < 4; s4++) {
                const float* gb = gs + (s4 * 32 + bl) * GS_PITCH;
                yi += gb[kk];
                yf += gb[16 + kk];
                yg += gb[32 + kk];
                yo += gb[48 + kk];
            }
            float ig = 1.f / (1.f + expf(-yi));
            float fg = 1.f / (1.f + expf(-yf));
            float gg = fmaxf(yg, 0.f);
            float og = 1.f / (1.f + expf(-yo));
            creg[r2] = fg * creg[r2] + ig * gg;
            hdst[(size_t)(p * BP + bl) * H_DIM + q * KP + kk] = og * creg[r2];
        }

        // Prefetch next step's x_proj (DRAM latency hides behind the barrier).
        if (t + 1 < S_DIM) {
            const float* xps = g_xp + ((size_t)(t + 1) * B_DIM + p * BP) * G4H;
#pragma unroll
            for (int r2 = 0; r2 < 2; r2++) {
                int bl = (tid + r2 * 256) >> 4;
#pragma unroll
                for (int g = 0; g < 4; g++)
                    xv[r2][g] = xps[(size_t)bl * G4H + g * 512 + q * KP + kk];
            }
        }
        __syncthreads();

        // Group barrier: 32 CTAs sharing batch part p. Monotonic, replay-safe.
        if (tid == 0) {
            __threadfence();
            unsigned long long* bar = &g_bar4[p * 16];
            unsigned long long ticket = atomicAdd(bar, 1ULL);
            unsigned long long target = (ticket / GRP + 1) * (unsigned long long)GRP;
            while (*(volatile unsigned long long*)bar < target) { }
            __threadfence();
        }
        __syncthreads();
    }
}

// ============================================================================
// Phase 3: out[b][o] = h_final[b] . fc_w[o] + fc_b[o]; h_final = g_h[1].
// ============================================================================
__global__ __launch_bounds__(320) void fc_kernel(const float* __restrict__ fcw,
                                                 const float* __restrict__ fcb,
                                                 float* __restrict__ out) {
    int b = blockIdx.x;
    int w = threadIdx.x >> 5, lane = threadIdx.x & 31;
    const float* h = g_h[1] + (size_t)b * H_DIM;
    float s = 0.f;
    for (int k = lane; k < H_DIM; k += 32) s += h[k] * fcw[w * H_DIM + k];
#pragma unroll
    for (int off = 16; off; off >>= 1) s += __shfl_down_sync(0xffffffffu, s, off);
    if (lane == 0) out[b * O_DIM + w] = s + fcb[w];
}

extern "C" void kernel_launch(void* const* d_in, const int* in_sizes, int n_in,
                              void* d_out, int out_size) {
    const float* x   = (const float*)d_in[0];
    const float* Wih = (const float*)d_in[1];
    const float* Whh = (const float*)d_in[2];
    const float* bih = (const float*)d_in[3];
    const float* bhh = (const float*)d_in[4];
    const float* fcw = (const float*)d_in[5];
    const float* fcb = (const float*)d_in[6];
    float* out = (float*)d_out;

    cudaFuncSetAttribute(lstm_kernel, cudaFuncAttributeMaxDynamicSharedMemorySize,
                         SMEM_LSTM_BYTES);

    xproj_kernel<<<dim3(16, 8, 128), 256>>>(x, Wih, bih, bhh);
    lstm_kernel<<<NCTA, 256, SMEM_LSTM_BYTES>>>(Whh);
    fc_kernel<<<B_DIM, 320>>>(fcw, fcb, out);
}

// round 12
// speedup vs baseline: 1.1088x; 1.1088x over previous
#include <cuda_runtime.h>
#include <cstdint>
#include <math.h>

// Problem dims
#define B_DIM 128
#define S_DIM 1024
#define I_DIM 256
#define H_DIM 512
#define G4H   2048
#define O_DIM 10

// Recurrence partition: 128 persistent CTAs = 4 batch parts x 32 k parts
#define NCTA   128
#define PPARTS 4
#define QPARTS 32
#define GRP    32           // CTAs per barrier group (one batch part)
#define BP (B_DIM/PPARTS)   // 32 batch rows per CTA
#define KP (H_DIM/QPARTS)   // 16 h-columns per CTA

#define WS_PITCH 516        // 512+4 pad: conflict-free fragment LDS, 2064B row (16B mult)
#define GS_PITCH 66

// smem: W slice [64][516] u32 + h tile [32][516] u32 + gate slabs [4][32][66] f32
#define SMEM_LSTM_BYTES ((64*WS_PITCH + 32*WS_PITCH)*4 + 4*32*GS_PITCH*4)
// xproj: double-buffered A/B tiles [2][128][36] each
#define SMEM_XP_BYTES (4 * 128 * 36 * 4)

// Scratch (device globals: the sanctioned no-alloc workaround)
__device__ float g_xp[(size_t)S_DIM * B_DIM * G4H];   // 1 GB: x_proj in [s][b][g]
__device__ float g_h[2][B_DIM * H_DIM];               // ping-pong h
__device__ unsigned long long g_bar4[64];             // 4 group barriers, 128B apart

__device__ __forceinline__ uint32_t f2tf(float x) {
    uint32_t r;
    asm("cvt.rna.tf32.f32 %0, %1;" : "=r"(r) : "f"(x));
    return r;
}

__device__ __forceinline__ void cpa16(uint32_t smem_dst, const void* gsrc) {
    asm volatile("cp.async.cg.shared.global [%0], [%1], 16;\n"
                 :: "r"(smem_dst), "l"(gsrc));
}
__device__ __forceinline__ void cpa_commit() {
    asm volatile("cp.async.commit_group;\n" ::: "memory");
}
template <int N>
__device__ __forceinline__ void cpa_wait() {
    asm volatile("cp.async.wait_group %0;\n" :: "n"(N) : "memory");
}

__device__ __forceinline__ void mma8(float& d0, float& d1, float& d2, float& d3,
                                     uint32_t a0, uint32_t a1, uint32_t a2, uint32_t a3,
                                     uint32_t b0, uint32_t b1) {
    asm volatile(
        "mma.sync.aligned.m16n8k8.row.col.f32.tf32.tf32.f32 "
        "{%0,%1,%2,%3},{%4,%5,%6,%7},{%8,%9},{%0,%1,%2,%3};"
        : "+f"(d0), "+f"(d1), "+f"(d2), "+f"(d3)
        : "r"(a0), "r"(a1), "r"(a2), "r"(a3), "r"(b0), "r"(b1));
}

// ============================================================================
// Phase 1: x_proj[s][b][g] = sum_i x[b][s][i]*W_ih[g][i] + b_ih[g] + b_hh[g]
// CTA: fixed s, M=128 batch rows (8KB-stride coalesced output), N=128 gate
// cols, K=256 in 8 chunks. 2-stage cp.async pipeline, raw fp32 bits as tf32.
// ============================================================================
__global__ __launch_bounds__(256) void xproj_kernel(
    const float* __restrict__ x, const float* __restrict__ Wih,
    const float* __restrict__ bih, const float* __restrict__ bhh) {
    extern __shared__ uint32_t smx[];
    // As buf: smx + buf*128*36 ; Bs buf: smx + (2+buf)*128*36
    const int s   = blockIdx.y;
    const int n0  = blockIdx.x * 128;
    const int tid = threadIdx.x;
    const int warp = tid >> 5, lane = tid & 31;
    const int gid = lane >> 2, tq = lane & 3;
    const int mw = warp >> 1, nw = warp & 1;   // 4 M-warps x 2 N-warps

    const uint32_t smx_base = (uint32_t)__cvta_generic_to_shared(smx);

    // issue cp.asyncs for k-chunk kc8 into buffer buf (A: 1024 16B, B: 1024 16B)
    auto load_chunk = [&](int kc8, int buf) {
        int kc = kc8 * 32;
#pragma unroll
        for (int j = 0; j < 4; j++) {
            int id = tid + 256 * j;            // 0..1023
            int r  = id >> 3;                  // row 0..127
            int c  = (id & 7) * 4;             // col 0..28
            cpa16(smx_base + (buf * 128 * 36 + r * 36 + c) * 4,
                  x + ((size_t)r * S_DIM + s) * I_DIM + kc + c);
            cpa16(smx_base + ((2 + buf) * 128 * 36 + r * 36 + c) * 4,
                  Wih + (size_t)(n0 + r) * I_DIM + kc + c);
        }
    };

    float acc[2][8][4] = {};

    load_chunk(0, 0);
    cpa_commit();

    for (int kc8 = 0; kc8 < 8; kc8++) {
        int cur = kc8 & 1;
        if (kc8 < 7) {
            load_chunk(kc8 + 1, cur ^ 1);
            cpa_commit();
            cpa_wait<1>();
        } else {
            cpa_wait<0>();
        }
        __syncthreads();

        const uint32_t* As = smx + cur * 128 * 36;
        const uint32_t* Bs = smx + (2 + cur) * 128 * 36;
#pragma unroll
        for (int ks = 0; ks < 32; ks += 8) {
            uint32_t a[2][4];
#pragma unroll
            for (int mt = 0; mt < 2; mt++) {
                int m0 = mw * 32 + mt * 16;
                a[mt][0] = As[(m0 + gid) * 36 + ks + tq];
                a[mt][1] = As[(m0 + gid + 8) * 36 + ks + tq];
                a[mt][2] = As[(m0 + gid) * 36 + ks + tq + 4];
                a[mt][3] = As[(m0 + gid + 8) * 36 + ks + tq + 4];
            }
#pragma unroll
            for (int nt = 0; nt < 8; nt++) {
                int nn = nw * 64 + nt * 8;
                uint32_t b0 = Bs[(nn + gid) * 36 + ks + tq];
                uint32_t b1 = Bs[(nn + gid) * 36 + ks + tq + 4];
                mma8(acc[0][nt][0], acc[0][nt][1], acc[0][nt][2], acc[0][nt][3],
                     a[0][0], a[0][1], a[0][2], a[0][3], b0, b1);
                mma8(acc[1][nt][0], acc[1][nt][1], acc[1][nt][2], acc[1][nt][3],
                     a[1][0], a[1][1], a[1][2], a[1][3], b0, b1);
            }
        }
        __syncthreads();
    }

#pragma unroll
    for (int mt = 0; mt < 2; mt++) {
        int row = mw * 32 + mt * 16 + gid;       // batch row
#pragma unroll
        for (int nt = 0; nt < 8; nt++) {
            int col = n0 + nw * 64 + nt * 8 + tq * 2;
            float bs0 = bih[col]     + bhh[col];
            float bs1 = bih[col + 1] + bhh[col + 1];
            size_t r0 = ((size_t)s * B_DIM + row) * G4H + col;
            size_t r1 = ((size_t)s * B_DIM + row + 8) * G4H + col;
            g_xp[r0]     = acc[mt][nt][0] + bs0;
            g_xp[r0 + 1] = acc[mt][nt][1] + bs1;
            g_xp[r1]     = acc[mt][nt][2] + bs0;
            g_xp[r1 + 1] = acc[mt][nt][3] + bs1;
        }
    }
}

// ============================================================================
// Phase 2: persistent recurrence. CTA (p,q): batch rows [p*32,+32), h-cols
// [q*16,+16). 8 warps = 4 k-parts x 2 n-halves. Warp pair kp stages ITS OWN
// 16KB h-chunk via cp.async (raw fp32 as tf32-RZ), wait_group 0 + named
// barrier(64) — no full-CTA sync before MMA. Cross-k partials reduced through
// 4 gs slabs. Group barrier over the 32 CTAs sharing a batch part.
// ============================================================================
__global__ __launch_bounds__(256, 1) void lstm_kernel(const float* __restrict__ Whh) {
    extern __shared__ uint32_t sm[];
    uint32_t* Ws = sm;                                   // [64][516]
    uint32_t* hs = sm + 64 * WS_PITCH;                   // [32][516]
    float*    gs = (float*)(sm + (64 + 32) * WS_PITCH);  // [4][32][66]

    const int tid  = threadIdx.x;
    const int warp = tid >> 5, lane = tid & 31;
    const int gid  = lane >> 2, tq = lane & 3;
    const int kp = warp & 3;         // k-part: K range [kp*128, kp*128+128)
    const int nh = warp >> 2;        // n-half: N cols [nh*32, nh*32+32)
    const int pl = nh * 32 + lane;   // lane id within the kp warp pair (0..63)
    const int q = blockIdx.x & (QPARTS - 1);
    const int p = blockIdx.x >> 5;

    const uint32_t hs_base = (uint32_t)__cvta_generic_to_shared(hs);

    // Load resident W_hh slice (tf32 RNA). Row r (0..63): gate r/16, k-col q*16 + r%16.
#pragma unroll
    for (int it = 0; it < 32; it++) {
        int id = tid + 256 * it;           // 8192 float4
        int r  = id >> 7;                  // 0..63
        int c4 = (id & 127) * 4;
        int grow = (r >> 4) * H_DIM + q * KP + (r & 15);
        float4 v = *reinterpret_cast<const float4*>(Whh + (size_t)grow * H_DIM + c4);
        uint32_t* d = Ws + r * WS_PITCH + c4;
        d[0] = f2tf(v.x); d[1] = f2tf(v.y); d[2] = f2tf(v.z); d[3] = f2tf(v.w);
    }

    // Persistent c-state: thread owns (b,k) pairs tid and tid+256.
    float creg[2] = {0.f, 0.f};
    const int kk = tid & 15;

    // Prefetch x_proj gate values for t=0.
    float xv[2][4];
    {
        const float* xps = g_xp + ((size_t)p * BP) * G4H;
#pragma unroll
        for (int r2 = 0; r2 < 2; r2++) {
            int bl = (tid + r2 * 256) >> 4;
#pragma unroll
            for (int g = 0; g < 4; g++)
                xv[r2][g] = xps[(size_t)bl * G4H + g * 512 + q * KP + kk];
        }
    }

    for (int t = 0; t < S_DIM; t++) {
        float acc[2][4][4] = {};
        if (t > 0) {
            // Stage this pair's h chunk: rows 0..31, cols [kp*128, kp*128+128).
            // 1024 16B copies over 64 threads = 16 each. Private to this pair.
            const float* hp = g_h[(t + 1) & 1] + (size_t)p * BP * H_DIM;
#pragma unroll
            for (int j = 0; j < 16; j++) {
                int id = pl + 64 * j;          // 0..1023
                int r  = id >> 5;              // 0..31
                int sg = (id & 31) * 4;        // col within chunk, 0..124
                cpa16(hs_base + (r * WS_PITCH + kp * 128 + sg) * 4,
                      hp + (size_t)r * H_DIM + kp * 128 + sg);
            }
            cpa_commit();
            cpa_wait<0>();
            asm volatile("bar.sync %0, 64;" :: "r"(1 + kp) : "memory");

#pragma unroll 4
            for (int ks = 0; ks < 16; ks++) {
                int k0 = kp * 128 + ks * 8;
                uint32_t a[2][4];
#pragma unroll
                for (int mt = 0; mt < 2; mt++) {
                    int m0 = mt * 16;
                    a[mt][0] = hs[(m0 + gid) * WS_PITCH + k0 + tq];
                    a[mt][1] = hs[(m0 + gid + 8) * WS_PITCH + k0 + tq];
                    a[mt][2] = hs[(m0 + gid) * WS_PITCH + k0 + tq + 4];
                    a[mt][3] = hs[(m0 + gid + 8) * WS_PITCH + k0 + tq + 4];
                }
#pragma unroll
                for (int nt = 0; nt < 4; nt++) {
                    int nn = nh * 32 + nt * 8;
                    uint32_t b0 = Ws[(nn + gid) * WS_PITCH + k0 + tq];
                    uint32_t b1 = Ws[(nn + gid) * WS_PITCH + k0 + tq + 4];
                    mma8(acc[0][nt][0], acc[0][nt][1], acc[0][nt][2], acc[0][nt][3],
                         a[0][0], a[0][1], a[0][2], a[0][3], b0, b1);
                    mma8(acc[1][nt][0], acc[1][nt][1], acc[1][nt][2], acc[1][nt][3],
                         a[1][0], a[1][1], a[1][2], a[1][3], b0, b1);
                }
            }
        }

        // Scatter k-part partials into slab kp (float2 stores).
        {
            float* gsp = gs + kp * 32 * GS_PITCH;
#pragma unroll
            for (int mt = 0; mt < 2; mt++) {
                int row = mt * 16 + gid;
#pragma unroll
                for (int nt = 0; nt < 4; nt++) {
                    int col = nh * 32 + nt * 8 + tq * 2;
                    *reinterpret_cast<float2*>(gsp + row * GS_PITCH + col) =
                        make_float2(acc[mt][nt][0], acc[mt][nt][1]);
                    *reinterpret_cast<float2*>(gsp + (row + 8) * GS_PITCH + col) =
                        make_float2(acc[mt][nt][2], acc[mt][nt][3]);
                }
            }
        }
        __syncthreads();

        // Elementwise: sum 4 k-slabs + x_proj, gate math, c update, h write.
        float* hdst = g_h[t & 1];
#pragma unroll
        for (int r2 = 0; r2 < 2; r2++) {
            int bl = (tid + r2 * 256) >> 4;
            float yi = xv[r2][0], yf = xv[r2][1], yg = xv[r2][2], yo = xv[r2][3];
#pragma unroll
            for (int s4 = 0; s4 < 4; s4++) {
                const float* gb = gs + (s4 * 32 + bl) * GS_PITCH;
                yi += gb[kk];
                yf += gb[16 + kk];
                yg += gb[32 + kk];
                yo += gb[48 + kk];
            }
            float ig = 1.f / (1.f + expf(-yi));
            float fg = 1.f / (1.f + expf(-yf));
            float gg = fmaxf(yg, 0.f);
            float og = 1.f / (1.f + expf(-yo));
            creg[r2] = fg * creg[r2] + ig * gg;
            hdst[(size_t)(p * BP + bl) * H_DIM + q * KP + kk] = og * creg[r2];
        }

        // Prefetch next step's x_proj (DRAM latency hides behind the barrier).
        if (t + 1 < S_DIM) {
            const float* xps = g_xp + ((size_t)(t + 1) * B_DIM + p * BP) * G4H;
#pragma unroll
            for (int r2 = 0; r2 < 2; r2++) {
                int bl = (tid + r2 * 256) >> 4;
#pragma unroll
                for (int g = 0; g < 4; g++)
                    xv[r2][g] = xps[(size_t)bl * G4H + g * 512 + q * KP + kk];
            }
        }
        __syncthreads();   // slabs consumed; safe to overwrite next step

        // Group barrier: 32 CTAs sharing batch part p. Monotonic, replay-safe.
        if (tid == 0) {
            __threadfence();
            unsigned long long* bar = &g_bar4[p * 16];
            unsigned long long ticket = atomicAdd(bar, 1ULL);
            unsigned long long target = (ticket / GRP + 1) * (unsigned long long)GRP;
            while (*(volatile unsigned long long*)bar < target) { }
            __threadfence();
        }
        __syncthreads();
    }
}

// ============================================================================
// Phase 3: out[b][o] = h_final[b] . fc_w[o] + fc_b[o]; h_final = g_h[1].
// ============================================================================
__global__ __launch_bounds__(320) void fc_kernel(const float* __restrict__ fcw,
                                                 const float* __restrict__ fcb,
                                                 float* __restrict__ out) {
    int b = blockIdx.x;
    int w = threadIdx.x >> 5, lane = threadIdx.x & 31;
    const float* h = g_h[1] + (size_t)b * H_DIM;
    float s = 0.f;
    for (int k = lane; k < H_DIM; k += 32) s += h[k] * fcw[w * H_DIM + k];
#pragma unroll
    for (int off = 16; off; off >>= 1) s += __shfl_down_sync(0xffffffffu, s, off);
    if (lane == 0) out[b * O_DIM + w] = s + fcb[w];
}

extern "C" void kernel_launch(void* const* d_in, const int* in_sizes, int n_in,
                              void* d_out, int out_size) {
    const float* x   = (const float*)d_in[0];
    const float* Wih = (const float*)d_in[1];
    const float* Whh = (const float*)d_in[2];
    const float* bih = (const float*)d_in[3];
    const float* bhh = (const float*)d_in[4];
    const float* fcw = (const float*)d_in[5];
    const float* fcb = (const float*)d_in[6];
    float* out = (float*)d_out;

    cudaFuncSetAttribute(xproj_kernel, cudaFuncAttributeMaxDynamicSharedMemorySize,
                         SMEM_XP_BYTES);
    cudaFuncSetAttribute(lstm_kernel, cudaFuncAttributeMaxDynamicSharedMemorySize,
                         SMEM_LSTM_BYTES);

    xproj_kernel<<<dim3(16, 1024), 256, SMEM_XP_BYTES>>>(x, Wih, bih, bhh);
    lstm_kernel<<<NCTA, 256, SMEM_LSTM_BYTES>>>(Whh);
    fc_kernel<<<B_DIM, 320>>>(fcw, fcb, out);
}

// round 14
// speedup vs baseline: 1.3131x; 1.1842x over previous
#include <cuda_runtime.h>
#include <cuda_fp16.h>
#include <cstdint>
#include <math.h>

// Problem dims
#define B_DIM 128
#define S_DIM 1024
#define I_DIM 256
#define H_DIM 512
#define G4H   2048
#define O_DIM 10

// Recurrence partition: 128 persistent CTAs = 4 batch parts x 32 k parts
#define NCTA   128
#define PPARTS 4
#define QPARTS 32
#define GRP    32           // CTAs per barrier group (one batch part)
#define BP (B_DIM/PPARTS)   // 32 batch rows per CTA
#define KP (H_DIM/QPARTS)   // 16 h-columns per CTA

#define W2_PITCH 260        // 256 half2 + 4 pad: (4*row+tq)%32 unique -> conflict-free
#define GS_PITCH 66

// smem: W slice [64][260] u32(half2) + h tile [32][260] u32 + gate slabs [4][32][66] f32
#define SMEM_LSTM_BYTES ((64*W2_PITCH + 32*W2_PITCH)*4 + 4*32*GS_PITCH*4)
// xproj: double-buffered A/B tiles [2][128][36] each
#define SMEM_XP_BYTES (4 * 128 * 36 * 4)

// Scratch (device globals: the sanctioned no-alloc workaround)
__device__ float g_xp[(size_t)S_DIM * B_DIM * G4H];        // 1 GB: x_proj [s][b][g]
__device__ __align__(256) __half g_h[2][B_DIM * H_DIM];    // ping-pong h (fp16)
__device__ unsigned long long g_bar4[64];                  // 4 group barriers, 128B apart

__device__ __forceinline__ void cpa16(uint32_t smem_dst, const void* gsrc) {
    asm volatile("cp.async.cg.shared.global [%0], [%1], 16;\n"
                 :: "r"(smem_dst), "l"(gsrc));
}
__device__ __forceinline__ void cpa_commit() {
    asm volatile("cp.async.commit_group;\n" ::: "memory");
}
template <int N>
__device__ __forceinline__ void cpa_wait() {
    asm volatile("cp.async.wait_group %0;\n" :: "n"(N) : "memory");
}

// tf32 mma (xproj). Operands are raw fp32 bits; caller pre-rounds with +0x1000 (RNA).
__device__ __forceinline__ void mma_tf32(float& d0, float& d1, float& d2, float& d3,
                                         uint32_t a0, uint32_t a1, uint32_t a2, uint32_t a3,
                                         uint32_t b0, uint32_t b1) {
    asm volatile(
        "mma.sync.aligned.m16n8k8.row.col.f32.tf32.tf32.f32 "
        "{%0,%1,%2,%3},{%4,%5,%6,%7},{%8,%9},{%0,%1,%2,%3};"
        : "+f"(d0), "+f"(d1), "+f"(d2), "+f"(d3)
        : "r"(a0), "r"(a1), "r"(a2), "r"(a3), "r"(b0), "r"(b1));
}

// fp16 mma with fp32 accumulate (recurrence)
__device__ __forceinline__ void mma_f16(float& d0, float& d1, float& d2, float& d3,
                                        uint32_t a0, uint32_t a1, uint32_t a2, uint32_t a3,
                                        uint32_t b0, uint32_t b1) {
    asm volatile(
        "mma.sync.aligned.m16n8k16.row.col.f32.f16.f16.f32 "
        "{%0,%1,%2,%3},{%4,%5,%6,%7},{%8,%9},{%0,%1,%2,%3};"
        : "+f"(d0), "+f"(d1), "+f"(d2), "+f"(d3)
        : "r"(a0), "r"(a1), "r"(a2), "r"(a3), "r"(b0), "r"(b1));
}

// ============================================================================
// Phase 1: x_proj[s][b][g] = sum_i x[b][s][i]*W_ih[g][i] + b_ih[g] + b_hh[g]
// CTA: fixed s, M=128 batch rows, N=128 gate cols, K=256 in 8 chunks.
// 2-stage cp.async pipeline; +0x1000 bit-round on fragments = tf32 RNA.
// ============================================================================
__global__ __launch_bounds__(256) void xproj_kernel(
    const float* __restrict__ x, const float* __restrict__ Wih,
    const float* __restrict__ bih, const float* __restrict__ bhh) {
    extern __shared__ uint32_t smx[];
    const int s   = blockIdx.y;
    const int n0  = blockIdx.x * 128;
    const int tid = threadIdx.x;
    const int warp = tid >> 5, lane = tid & 31;
    const int gid = lane >> 2, tq = lane & 3;
    const int mw = warp >> 1, nw = warp & 1;   // 4 M-warps x 2 N-warps

    const uint32_t smx_base = (uint32_t)__cvta_generic_to_shared(smx);

    auto load_chunk = [&](int kc8, int buf) {
        int kc = kc8 * 32;
#pragma unroll
        for (int j = 0; j < 4; j++) {
            int id = tid + 256 * j;            // 0..1023
            int r  = id >> 3;                  // row 0..127
            int c  = (id & 7) * 4;             // col 0..28
            cpa16(smx_base + (buf * 128 * 36 + r * 36 + c) * 4,
                  x + ((size_t)r * S_DIM + s) * I_DIM + kc + c);
            cpa16(smx_base + ((2 + buf) * 128 * 36 + r * 36 + c) * 4,
                  Wih + (size_t)(n0 + r) * I_DIM + kc + c);
        }
    };

    float acc[2][8][4] = {};

    load_chunk(0, 0);
    cpa_commit();

    for (int kc8 = 0; kc8 < 8; kc8++) {
        int cur = kc8 & 1;
        if (kc8 < 7) {
            load_chunk(kc8 + 1, cur ^ 1);
            cpa_commit();
            cpa_wait<1>();
        } else {
            cpa_wait<0>();
        }
        __syncthreads();

        const uint32_t* As = smx + cur * 128 * 36;
        const uint32_t* Bs = smx + (2 + cur) * 128 * 36;
#pragma unroll
        for (int ks = 0; ks < 32; ks += 8) {
            uint32_t a[2][4];
#pragma unroll
            for (int mt = 0; mt < 2; mt++) {
                int m0 = mw * 32 + mt * 16;
                a[mt][0] = As[(m0 + gid) * 36 + ks + tq]     + 0x1000u;
                a[mt][1] = As[(m0 + gid + 8) * 36 + ks + tq] + 0x1000u;
                a[mt][2] = As[(m0 + gid) * 36 + ks + tq + 4] + 0x1000u;
                a[mt][3] = As[(m0 + gid + 8) * 36 + ks + tq + 4] + 0x1000u;
            }
#pragma unroll
            for (int nt = 0; nt < 8; nt++) {
                int nn = nw * 64 + nt * 8;
                uint32_t b0 = Bs[(nn + gid) * 36 + ks + tq]     + 0x1000u;
                uint32_t b1 = Bs[(nn + gid) * 36 + ks + tq + 4] + 0x1000u;
                mma_tf32(acc[0][nt][0], acc[0][nt][1], acc[0][nt][2], acc[0][nt][3],
                         a[0][0], a[0][1], a[0][2], a[0][3], b0, b1);
                mma_tf32(acc[1][nt][0], acc[1][nt][1], acc[1][nt][2], acc[1][nt][3],
                         a[1][0], a[1][1], a[1][2], a[1][3], b0, b1);
            }
        }
        __syncthreads();
    }

#pragma unroll
    for (int mt = 0; mt < 2; mt++) {
        int row = mw * 32 + mt * 16 + gid;       // batch row
#pragma unroll
        for (int nt = 0; nt < 8; nt++) {
            int col = n0 + nw * 64 + nt * 8 + tq * 2;
            float bs0 = bih[col]     + bhh[col];
            float bs1 = bih[col + 1] + bhh[col + 1];
            size_t r0 = ((size_t)s * B_DIM + row) * G4H + col;
            size_t r1 = ((size_t)s * B_DIM + row + 8) * G4H + col;
            g_xp[r0]     = acc[mt][nt][0] + bs0;
            g_xp[r0 + 1] = acc[mt][nt][1] + bs1;
            g_xp[r1]     = acc[mt][nt][2] + bs0;
            g_xp[r1 + 1] = acc[mt][nt][3] + bs1;
        }
    }
}

// ============================================================================
// Phase 2: persistent recurrence, fp16 m16n8k16 / fp32 accum.
// CTA (p,q): batch rows [p*32,+32), h-cols [q*16,+16). 8 warps = 4 k-parts x
// 2 n-halves. Warp pair kp cp.asyncs ITS OWN 8KB fp16 h-chunk, wait_group 0 +
// named barrier(64). Cross-k partials reduced through 4 f32 gs slabs.
// Group barrier over the 32 CTAs sharing a batch part.
// ============================================================================
__global__ __launch_bounds__(256, 1) void lstm_kernel(const float* __restrict__ Whh) {
    extern __shared__ uint32_t sm[];
    uint32_t* Ws = sm;                                   // [64][260] half2
    uint32_t* hs = sm + 64 * W2_PITCH;                   // [32][260] half2
    float*    gs = (float*)(sm + (64 + 32) * W2_PITCH);  // [4][32][66]

    const int tid  = threadIdx.x;
    const int warp = tid >> 5, lane = tid & 31;
    const int gid  = lane >> 2, tq = lane & 3;
    const int kp = warp & 3;         // k-part: K range [kp*128, kp*128+128)
    const int nh = warp >> 2;        // n-half: N cols [nh*32, nh*32+32)
    const int pl = nh * 32 + lane;   // lane id within the kp warp pair (0..63)
    const int q = blockIdx.x & (QPARTS - 1);
    const int p = blockIdx.x >> 5;

    const uint32_t hs_base = (uint32_t)__cvta_generic_to_shared(hs);

    // Load resident W_hh slice as half2 (RNE). Row r (0..63): gate r/16, k-col q*16 + r%16.
#pragma unroll
    for (int it = 0; it < 64; it++) {
        int id = tid + 256 * it;           // 0..16383
        int r  = id >> 8;                  // 0..63
        int c2 = id & 255;                 // half2 index 0..255
        int grow = (r >> 4) * H_DIM + q * KP + (r & 15);
        float f0 = Whh[(size_t)grow * H_DIM + 2 * c2];
        float f1 = Whh[(size_t)grow * H_DIM + 2 * c2 + 1];
        __half2 hv = __floats2half2_rn(f0, f1);
        Ws[r * W2_PITCH + c2] = *reinterpret_cast<uint32_t*>(&hv);
    }

    // Persistent c-state: thread owns (b,k) pairs tid and tid+256.
    float creg[2] = {0.f, 0.f};
    const int kk = tid & 15;

    // Prefetch x_proj gate values for t=0.
    float xv[2][4];
    {
        const float* xps = g_xp + ((size_t)p * BP) * G4H;
#pragma unroll
        for (int r2 = 0; r2 < 2; r2++) {
            int bl = (tid + r2 * 256) >> 4;
#pragma unroll
            for (int g = 0; g < 4; g++)
                xv[r2][g] = xps[(size_t)bl * G4H + g * 512 + q * KP + kk];
        }
    }

    for (int t = 0; t < S_DIM; t++) {
        float acc[2][4][4] = {};
        if (t > 0) {
            // Stage this pair's fp16 h chunk: rows 0..31, halves [kp*128, +128).
            // 8KB = 512 x 16B over 64 threads = 8 each.
            const __half* hp = g_h[(t + 1) & 1] + (size_t)p * BP * H_DIM;
#pragma unroll
            for (int j = 0; j < 8; j++) {
                int id = pl + 64 * j;          // 0..511
                int r  = id >> 4;              // 0..31
                int c8 = (id & 15) * 8;        // half offset in chunk, step 8
                cpa16(hs_base + (r * W2_PITCH + kp * 64 + (c8 >> 1)) * 4,
                      hp + (size_t)r * H_DIM + kp * 128 + c8);
            }
            cpa_commit();
            cpa_wait<0>();
            asm volatile("bar.sync %0, 64;" :: "r"(1 + kp) : "memory");

#pragma unroll
            for (int ks = 0; ks < 8; ks++) {
                int k0u = kp * 64 + ks * 8;    // half2 index of this k16 step
                uint32_t a[2][4];
#pragma unroll
                for (int mt = 0; mt < 2; mt++) {
                    int m0 = mt * 16;
                    a[mt][0] = hs[(m0 + gid) * W2_PITCH + k0u + tq];
                    a[mt][1] = hs[(m0 + gid + 8) * W2_PITCH + k0u + tq];
                    a[mt][2] = hs[(m0 + gid) * W2_PITCH + k0u + tq + 4];
                    a[mt][3] = hs[(m0 + gid + 8) * W2_PITCH + k0u + tq + 4];
                }
#pragma unroll
                for (int nt = 0; nt < 4; nt++) {
                    int nn = nh * 32 + nt * 8;
                    uint32_t b0 = Ws[(nn + gid) * W2_PITCH + k0u + tq];
                    uint32_t b1 = Ws[(nn + gid) * W2_PITCH + k0u + tq + 4];
                    mma_f16(acc[0][nt][0], acc[0][nt][1], acc[0][nt][2], acc[0][nt][3],
                            a[0][0], a[0][1], a[0][2], a[0][3], b0, b1);
                    mma_f16(acc[1][nt][0], acc[1][nt][1], acc[1][nt][2], acc[1][nt][3],
                            a[1][0], a[1][1], a[1][2], a[1][3], b0, b1);
                }
            }
        }

        // Scatter k-part partials into slab kp (float2 stores).
        {
            float* gsp = gs + kp * 32 * GS_PITCH;
#pragma unroll
            for (int mt = 0; mt < 2; mt++) {
                int row = mt * 16 + gid;
#pragma unroll
                for (int nt = 0; nt < 4; nt++) {
                    int col = nh * 32 + nt * 8 + tq * 2;
                    *reinterpret_cast<float2*>(gsp + row * GS_PITCH + col) =
                        make_float2(acc[mt][nt][0], acc[mt][nt][1]);
                    *reinterpret_cast<float2*>(gsp + (row + 8) * GS_PITCH + col) =
                        make_float2(acc[mt][nt][2], acc[mt][nt][3]);
                }
            }
        }
        __syncthreads();

        // Elementwise: sum 4 k-slabs + x_proj, gate math, c update, h write (fp16 RNE).
        __half* hdst = g_h[t & 1];
#pragma unroll
        for (int r2 = 0; r2 < 2; r2++) {
            int bl = (tid + r2 * 256) >> 4;
            float yi = xv[r2][0], yf = xv[r2][1], yg = xv[r2][2], yo = xv[r2][3];
#pragma unroll
            for (int s4 = 0; s4 < 4; s4++) {
                const float* gb = gs + (s4 * 32 + bl) * GS_PITCH;
                yi += gb[kk];
                yf += gb[16 + kk];
                yg += gb[32 + kk];
                yo += gb[48 + kk];
            }
            float ig = 1.f / (1.f + expf(-yi));
            float fg = 1.f / (1.f + expf(-yf));
            float gg = fmaxf(yg, 0.f);
            float og = 1.f / (1.f + expf(-yo));
            creg[r2] = fg * creg[r2] + ig * gg;
            hdst[(size_t)(p * BP + bl) * H_DIM + q * KP + kk] = __float2half_rn(og * creg[r2]);
        }

        // Prefetch next step's x_proj (DRAM latency hides behind the barrier).
        if (t + 1 < S_DIM) {
            const float* xps = g_xp + ((size_t)(t + 1) * B_DIM + p * BP) * G4H;
#pragma unroll
            for (int r2 = 0; r2 < 2; r2++) {
                int bl = (tid + r2 * 256) >> 4;
#pragma unroll
                for (int g = 0; g < 4; g++)
                    xv[r2][g] = xps[(size_t)bl * G4H + g * 512 + q * KP + kk];
            }
        }
        __syncthreads();   // slabs consumed; safe to overwrite next step

        // Group barrier: 32 CTAs sharing batch part p. Monotonic, replay-safe.
        if (tid == 0) {
            __threadfence();
            unsigned long long* bar = &g_bar4[p * 16];
            unsigned long long ticket = atomicAdd(bar, 1ULL);
            unsigned long long target = (ticket / GRP + 1) * (unsigned long long)GRP;
            while (*(volatile unsigned long long*)bar < target) { }
            __threadfence();
        }
        __syncthreads();
    }
}

// ============================================================================
// Phase 3: out[b][o] = h_final[b] . fc_w[o] + fc_b[o]; h_final = g_h[1].
// ============================================================================
__global__ __launch_bounds__(320) void fc_kernel(const float* __restrict__ fcw,
                                                 const float* __restrict__ fcb,
                                                 float* __restrict__ out) {
    int b = blockIdx.x;
    int w = threadIdx.x >> 5, lane = threadIdx.x & 31;
    const __half* h = g_h[1] + (size_t)b * H_DIM;
    float s = 0.f;
    for (int k = lane; k < H_DIM; k += 32) s += __half2float(h[k]) * fcw[w * H_DIM + k];
#pragma unroll
    for (int off = 16; off; off >>= 1) s += __shfl_down_sync(0xffffffffu, s, off);
    if (lane == 0) out[b * O_DIM + w] = s + fcb[w];
}

extern "C" void kernel_launch(void* const* d_in, const int* in_sizes, int n_in,
                              void* d_out, int out_size) {
    const float* x   = (const float*)d_in[0];
    const float* Wih = (const float*)d_in[1];
    const float* Whh = (const float*)d_in[2];
    const float* bih = (const float*)d_in[3];
    const float* bhh = (const float*)d_in[4];
    const float* fcw = (const float*)d_in[5];
    const float* fcb = (const float*)d_in[6];
    float* out = (float*)d_out;

    cudaFuncSetAttribute(xproj_kernel, cudaFuncAttributeMaxDynamicSharedMemorySize,
                         SMEM_XP_BYTES);
    cudaFuncSetAttribute(lstm_kernel, cudaFuncAttributeMaxDynamicSharedMemorySize,
                         SMEM_LSTM_BYTES);

    xproj_kernel<<<dim3(16, 1024), 256, SMEM_XP_BYTES>>>(x, Wih, bih, bhh);
    lstm_kernel<<<NCTA, 256, SMEM_LSTM_BYTES>>>(Whh);
    fc_kernel<<<B_DIM, 320>>>(fcw, fcb, out);
}

// round 15
// speedup vs baseline: 1.3680x; 1.0418x over previous
#include <cuda_runtime.h>
#include <cuda_fp16.h>
#include <cstdint>
#include <math.h>

// Problem dims
#define B_DIM 128
#define S_DIM 1024
#define I_DIM 256
#define H_DIM 512
#define G4H   2048
#define O_DIM 10

// Recurrence partition: 128 persistent CTAs = 4 batch parts x 32 k parts
#define NCTA   128
#define PPARTS 4
#define QPARTS 32
#define GRP    32           // CTAs per barrier group (one batch part)
#define BP (B_DIM/PPARTS)   // 32 batch rows per CTA
#define KP (H_DIM/QPARTS)   // 16 h-columns per CTA

#define W2_PITCH 260        // 256 half2 + 4 pad -> conflict-free fragment LDS
#define GS_PITCH 66

// smem: W slice [64][260] u32(half2) + h tile [32][260] u32 + gate slabs [4][32][66] f32
#define SMEM_LSTM_BYTES ((64*W2_PITCH + 32*W2_PITCH)*4 + 4*32*GS_PITCH*4)
// xproj: double-buffered A/B half tiles [2][128][36] u32 each
#define SMEM_XP_BYTES (4 * 128 * 36 * 4)

// Scratch (device globals: the sanctioned no-alloc workaround)
__device__ float g_xp[(size_t)S_DIM * B_DIM * G4H];        // 1 GB: x_proj [s][b][g]
__device__ __align__(256) __half g_x16[(size_t)B_DIM * S_DIM * I_DIM];  // fp16 x
__device__ __align__(256) __half g_w16[(size_t)G4H * I_DIM];            // fp16 W_ih
__device__ __align__(256) __half g_h[2][B_DIM * H_DIM];    // ping-pong h (fp16)
__device__ unsigned long long g_bar4[64];                  // 4 group barriers (monotonic)
__device__ uint32_t g_flag[PPARTS * QPARTS * 32];          // per-CTA step flags, 128B apart

__device__ __forceinline__ void cpa16(uint32_t smem_dst, const void* gsrc) {
    asm volatile("cp.async.cg.shared.global [%0], [%1], 16;\n"
                 :: "r"(smem_dst), "l"(gsrc));
}
__device__ __forceinline__ void cpa_commit() {
    asm volatile("cp.async.commit_group;\n" ::: "memory");
}
template <int N>
__device__ __forceinline__ void cpa_wait() {
    asm volatile("cp.async.wait_group %0;\n" :: "n"(N) : "memory");
}
__device__ __forceinline__ uint32_t ld_acq(const uint32_t* p) {
    uint32_t v;
    asm volatile("ld.acquire.gpu.global.b32 %0, [%1];" : "=r"(v) : "l"(p) : "memory");
    return v;
}
__device__ __forceinline__ void st_rel(uint32_t* p, uint32_t v) {
    asm volatile("st.release.gpu.global.b32 [%0], %1;" :: "l"(p), "r"(v) : "memory");
}

// fp16 mma with fp32 accumulate
__device__ __forceinline__ void mma_f16(float& d0, float& d1, float& d2, float& d3,
                                        uint32_t a0, uint32_t a1, uint32_t a2, uint32_t a3,
                                        uint32_t b0, uint32_t b1) {
    asm volatile(
        "mma.sync.aligned.m16n8k16.row.col.f32.f16.f16.f32 "
        "{%0,%1,%2,%3},{%4,%5,%6,%7},{%8,%9},{%0,%1,%2,%3};"
        : "+f"(d0), "+f"(d1), "+f"(d2), "+f"(d3)
        : "r"(a0), "r"(a1), "r"(a2), "r"(a3), "r"(b0), "r"(b1));
}

// ============================================================================
// Phase 0: fp16 pre-conversion of x and W_ih (RNE).
// ============================================================================
__global__ __launch_bounds__(256) void cvt_x_kernel(const float* __restrict__ x) {
    size_t i = (size_t)blockIdx.x * 256 + threadIdx.x;   // 4194304 threads, 8 elems each
    const float4* src = reinterpret_cast<const float4*>(x) + i * 2;
    float4 v0 = src[0], v1 = src[1];
    __half2 h0 = __floats2half2_rn(v0.x, v0.y);
    __half2 h1 = __floats2half2_rn(v0.z, v0.w);
    __half2 h2 = __floats2half2_rn(v1.x, v1.y);
    __half2 h3 = __floats2half2_rn(v1.z, v1.w);
    uint4 o;
    o.x = *reinterpret_cast<uint32_t*>(&h0);
    o.y = *reinterpret_cast<uint32_t*>(&h1);
    o.z = *reinterpret_cast<uint32_t*>(&h2);
    o.w = *reinterpret_cast<uint32_t*>(&h3);
    reinterpret_cast<uint4*>(g_x16)[i] = o;
}

__global__ __launch_bounds__(256) void cvt_w_kernel(const float* __restrict__ Wih) {
    size_t i = (size_t)blockIdx.x * 256 + threadIdx.x;   // 131072 threads, 4 elems each
    float4 v = reinterpret_cast<const float4*>(Wih)[i];
    __half2 h0 = __floats2half2_rn(v.x, v.y);
    __half2 h1 = __floats2half2_rn(v.z, v.w);
    uint2 o;
    o.x = *reinterpret_cast<uint32_t*>(&h0);
    o.y = *reinterpret_cast<uint32_t*>(&h1);
    reinterpret_cast<uint2*>(g_w16)[i] = o;
}

// ============================================================================
// Phase 1: x_proj[s][b][g] = sum_i x[b][s][i]*W_ih[g][i] + b_ih[g] + b_hh[g]
// fp16 m16n8k16, fp32 accum. CTA: fixed s, M=128 batch, N=128 gate cols,
// K=256 halves in 4 chunks of 64. 2-stage cp.async pipeline.
// ============================================================================
__global__ __launch_bounds__(256) void xproj_kernel(
    const float* __restrict__ bih, const float* __restrict__ bhh) {
    extern __shared__ uint32_t smx[];
    const int s   = blockIdx.y;
    const int n0  = blockIdx.x * 128;
    const int tid = threadIdx.x;
    const int warp = tid >> 5, lane = tid & 31;
    const int gid = lane >> 2, tq = lane & 3;
    const int mw = warp >> 1, nw = warp & 1;   // 4 M-warps x 2 N-warps

    const uint32_t smx_base = (uint32_t)__cvta_generic_to_shared(smx);

    // chunk kc4 (0..3) = 64 halves of K. A: batch rows; B: gate rows.
    auto load_chunk = [&](int kc4, int buf) {
        int kc = kc4 * 64;
#pragma unroll
        for (int j = 0; j < 4; j++) {
            int id = tid + 256 * j;            // 0..1023
            int r  = id >> 3;                  // row 0..127
            int c  = id & 7;                   // 8-half group
            cpa16(smx_base + (buf * 128 * 36 + r * 36 + c * 4) * 4,
                  g_x16 + ((size_t)r * S_DIM + s) * I_DIM + kc + c * 8);
            cpa16(smx_base + ((2 + buf) * 128 * 36 + r * 36 + c * 4) * 4,
                  g_w16 + (size_t)(n0 + r) * I_DIM + kc + c * 8);
        }
    };

    float acc[2][8][4] = {};

    load_chunk(0, 0);
    cpa_commit();

    for (int kc4 = 0; kc4 < 4; kc4++) {
        int cur = kc4 & 1;
        if (kc4 < 3) {
            load_chunk(kc4 + 1, cur ^ 1);
            cpa_commit();
            cpa_wait<1>();
        } else {
            cpa_wait<0>();
        }
        __syncthreads();

        const uint32_t* As = smx + cur * 128 * 36;
        const uint32_t* Bs = smx + (2 + cur) * 128 * 36;
#pragma unroll
        for (int ks = 0; ks < 4; ks++) {        // 4 k16 steps per chunk
            int k2 = ks * 8;                    // half2 base
            uint32_t a[2][4];
#pragma unroll
            for (int mt = 0; mt < 2; mt++) {
                int m0 = mw * 32 + mt * 16;
                a[mt][0] = As[(m0 + gid) * 36 + k2 + tq];
                a[mt][1] = As[(m0 + gid + 8) * 36 + k2 + tq];
                a[mt][2] = As[(m0 + gid) * 36 + k2 + tq + 4];
                a[mt][3] = As[(m0 + gid + 8) * 36 + k2 + tq + 4];
            }
#pragma unroll
            for (int nt = 0; nt < 8; nt++) {
                int nn = nw * 64 + nt * 8;
                uint32_t b0 = Bs[(nn + gid) * 36 + k2 + tq];
                uint32_t b1 = Bs[(nn + gid) * 36 + k2 + tq + 4];
                mma_f16(acc[0][nt][0], acc[0][nt][1], acc[0][nt][2], acc[0][nt][3],
                        a[0][0], a[0][1], a[0][2], a[0][3], b0, b1);
                mma_f16(acc[1][nt][0], acc[1][nt][1], acc[1][nt][2], acc[1][nt][3],
                        a[1][0], a[1][1], a[1][2], a[1][3], b0, b1);
            }
        }
        __syncthreads();
    }

#pragma unroll
    for (int mt = 0; mt < 2; mt++) {
        int row = mw * 32 + mt * 16 + gid;       // batch row
#pragma unroll
        for (int nt = 0; nt < 8; nt++) {
            int col = n0 + nw * 64 + nt * 8 + tq * 2;
            float bs0 = bih[col]     + bhh[col];
            float bs1 = bih[col + 1] + bhh[col + 1];
            size_t r0 = ((size_t)s * B_DIM + row) * G4H + col;
            size_t r1 = ((size_t)s * B_DIM + row + 8) * G4H + col;
            g_xp[r0]     = acc[mt][nt][0] + bs0;
            g_xp[r0 + 1] = acc[mt][nt][1] + bs1;
            g_xp[r1]     = acc[mt][nt][2] + bs0;
            g_xp[r1 + 1] = acc[mt][nt][3] + bs1;
        }
    }
}

// ============================================================================
// Phase 2: persistent recurrence, fp16 m16n8k16 / fp32 accum.
// NO per-step group barrier: per-CTA monotonic step flags (release/acquire).
// Warp pair kp waits only on its 8 producer CTAs' flags, then cp.asyncs its
// private 8KB h-chunk. 2-buffer ping-pong is race-free because step-t
// consumption transitively orders all group CTAs' step-(t-1) completion.
// ============================================================================
__global__ __launch_bounds__(256, 1) void lstm_kernel(const float* __restrict__ Whh) {
    extern __shared__ uint32_t sm[];
    uint32_t* Ws = sm;                                   // [64][260] half2
    uint32_t* hs = sm + 64 * W2_PITCH;                   // [32][260] half2
    float*    gs = (float*)(sm + (64 + 32) * W2_PITCH);  // [4][32][66]

    const int tid  = threadIdx.x;
    const int warp = tid >> 5, lane = tid & 31;
    const int gid  = lane >> 2, tq = lane & 3;
    const int kp = warp & 3;         // k-part: K range [kp*128, kp*128+128)
    const int nh = warp >> 2;        // n-half: N cols [nh*32, nh*32+32)
    const int pl = nh * 32 + lane;   // lane id within the kp warp pair (0..63)
    const int q = blockIdx.x & (QPARTS - 1);
    const int p = blockIdx.x >> 5;

    const uint32_t hs_base = (uint32_t)__cvta_generic_to_shared(hs);
    uint32_t* myflag = &g_flag[(p * QPARTS + q) * 32];
    const uint32_t* prodflag = &g_flag[(p * QPARTS + kp * 8 + (lane & 7)) * 32];

    // Reset own flag for this launch (replay safety).
    if (tid == 0) *myflag = 0;

    // Load resident W_hh slice as half2 (RNE). Row r (0..63): gate r/16, k-col q*16 + r%16.
#pragma unroll
    for (int it = 0; it < 64; it++) {
        int id = tid + 256 * it;           // 0..16383
        int r  = id >> 8;                  // 0..63
        int c2 = id & 255;                 // half2 index 0..255
        int grow = (r >> 4) * H_DIM + q * KP + (r & 15);
        float f0 = Whh[(size_t)grow * H_DIM + 2 * c2];
        float f1 = Whh[(size_t)grow * H_DIM + 2 * c2 + 1];
        __half2 hv = __floats2half2_rn(f0, f1);
        Ws[r * W2_PITCH + c2] = *reinterpret_cast<uint32_t*>(&hv);
    }

    // One group barrier: all 32 CTAs' flag resets visible before any polling.
    __syncthreads();
    if (tid == 0) {
        __threadfence();
        unsigned long long* bar = &g_bar4[p * 16];
        unsigned long long ticket = atomicAdd(bar, 1ULL);
        unsigned long long target = (ticket / GRP + 1) * (unsigned long long)GRP;
        while (*(volatile unsigned long long*)bar < target) { }
        __threadfence();
    }
    __syncthreads();

    // Persistent c-state: thread owns (b,k) pairs tid and tid+256.
    float creg[2] = {0.f, 0.f};
    const int kk = tid & 15;

    // Prefetch x_proj gate values for t=0.
    float xv[2][4];
    {
        const float* xps = g_xp + ((size_t)p * BP) * G4H;
#pragma unroll
        for (int r2 = 0; r2 < 2; r2++) {
            int bl = (tid + r2 * 256) >> 4;
#pragma unroll
            for (int g = 0; g < 4; g++)
                xv[r2][g] = xps[(size_t)bl * G4H + g * 512 + q * KP + kk];
        }
    }

    for (int t = 0; t < S_DIM; t++) {
        float acc[2][4][4] = {};
        if (t > 0) {
            // Wait for our 8 producers to have published h_{t-1} (flag >= t).
            if (lane < 8) {
                while (ld_acq(prodflag) < (uint32_t)t) { }
            }
            asm volatile("bar.sync %0, 64;" :: "r"(1 + kp) : "memory");

            // Stage this pair's fp16 h chunk: rows 0..31, halves [kp*128, +128).
            const __half* hp = g_h[(t + 1) & 1] + (size_t)p * BP * H_DIM;
#pragma unroll
            for (int j = 0; j < 8; j++) {
                int id = pl + 64 * j;          // 0..511
                int r  = id >> 4;              // 0..31
                int c8 = (id & 15) * 8;        // half offset in chunk
                cpa16(hs_base + (r * W2_PITCH + kp * 64 + (c8 >> 1)) * 4,
                      hp + (size_t)r * H_DIM + kp * 128 + c8);
            }
            cpa_commit();
            cpa_wait<0>();
            asm volatile("bar.sync %0, 64;" :: "r"(1 + kp) : "memory");

#pragma unroll
            for (int ks = 0; ks < 8; ks++) {
                int k0u = kp * 64 + ks * 8;    // half2 index of this k16 step
                uint32_t a[2][4];
#pragma unroll
                for (int mt = 0; mt < 2; mt++) {
                    int m0 = mt * 16;
                    a[mt][0] = hs[(m0 + gid) * W2_PITCH + k0u + tq];
                    a[mt][1] = hs[(m0 + gid + 8) * W2_PITCH + k0u + tq];
                    a[mt][2] = hs[(m0 + gid) * W2_PITCH + k0u + tq + 4];
                    a[mt][3] = hs[(m0 + gid + 8) * W2_PITCH + k0u + tq + 4];
                }
#pragma unroll
                for (int nt = 0; nt < 4; nt++) {
                    int nn = nh * 32 + nt * 8;
                    uint32_t b0 = Ws[(nn + gid) * W2_PITCH + k0u + tq];
                    uint32_t b1 = Ws[(nn + gid) * W2_PITCH + k0u + tq + 4];
                    mma_f16(acc[0][nt][0], acc[0][nt][1], acc[0][nt][2], acc[0][nt][3],
                            a[0][0], a[0][1], a[0][2], a[0][3], b0, b1);
                    mma_f16(acc[1][nt][0], acc[1][nt][1], acc[1][nt][2], acc[1][nt][3],
                            a[1][0], a[1][1], a[1][2], a[1][3], b0, b1);
                }
            }
        }

        // Scatter k-part partials into slab kp (float2 stores).
        {
            float* gsp = gs + kp * 32 * GS_PITCH;
#pragma unroll
            for (int mt = 0; mt < 2; mt++) {
                int row = mt * 16 + gid;
#pragma unroll
                for (int nt = 0; nt < 4; nt++) {
                    int col = nh * 32 + nt * 8 + tq * 2;
                    *reinterpret_cast<float2*>(gsp + row * GS_PITCH + col) =
                        make_float2(acc[mt][nt][0], acc[mt][nt][1]);
                    *reinterpret_cast<float2*>(gsp + (row + 8) * GS_PITCH + col) =
                        make_float2(acc[mt][nt][2], acc[mt][nt][3]);
                }
            }
        }
        __syncthreads();

        // Elementwise: sum 4 k-slabs + x_proj, gate math, c update, h write (fp16 RNE).
        __half* hdst = g_h[t & 1];
#pragma unroll
        for (int r2 = 0; r2 < 2; r2++) {
            int bl = (tid + r2 * 256) >> 4;
            float yi = xv[r2][0], yf = xv[r2][1], yg = xv[r2][2], yo = xv[r2][3];
#pragma unroll
            for (int s4 = 0; s4 < 4; s4++) {
                const float* gb = gs + (s4 * 32 + bl) * GS_PITCH;
                yi += gb[kk];
                yf += gb[16 + kk];
                yg += gb[32 + kk];
                yo += gb[48 + kk];
            }
            float ig = 1.f / (1.f + expf(-yi));
            float fg = 1.f / (1.f + expf(-yf));
            float gg = fmaxf(yg, 0.f);
            float og = 1.f / (1.f + expf(-yo));
            creg[r2] = fg * creg[r2] + ig * gg;
            hdst[(size_t)(p * BP + bl) * H_DIM + q * KP + kk] = __float2half_rn(og * creg[r2]);
        }
        __threadfence();   // each thread: h stores globally ordered before flag release

        // Prefetch next step's x_proj (hides DRAM latency behind publish/poll).
        if (t + 1 < S_DIM) {
            const float* xps = g_xp + ((size_t)(t + 1) * B_DIM + p * BP) * G4H;
#pragma unroll
            for (int r2 = 0; r2 < 2; r2++) {
                int bl = (tid + r2 * 256) >> 4;
#pragma unroll
                for (int g = 0; g < 4; g++)
                    xv[r2][g] = xps[(size_t)bl * G4H + g * 512 + q * KP + kk];
            }
        }
        __syncthreads();   // all h writes + fences done; slabs consumed

        // Publish h_t.
        if (tid == 0) st_rel(myflag, (uint32_t)(t + 1));
    }
}

// ============================================================================
// Phase 3: out[b][o] = h_final[b] . fc_w[o] + fc_b[o]; h_final = g_h[1].
// ============================================================================
__global__ __launch_bounds__(320) void fc_kernel(const float* __restrict__ fcw,
                                                 const float* __restrict__ fcb,
                                                 float* __restrict__ out) {
    int b = blockIdx.x;
    int w = threadIdx.x >> 5, lane = threadIdx.x & 31;
    const __half* h = g_h[1] + (size_t)b * H_DIM;
    float s = 0.f;
    for (int k = lane; k < H_DIM; k += 32) s += __half2float(h[k]) * fcw[w * H_DIM + k];
#pragma unroll
    for (int off = 16; off; off >>= 1) s += __shfl_down_sync(0xffffffffu, s, off);
    if (lane == 0) out[b * O_DIM + w] = s + fcb[w];
}

extern "C" void kernel_launch(void* const* d_in, const int* in_sizes, int n_in,
                              void* d_out, int out_size) {
    const float* x   = (const float*)d_in[0];
    const float* Wih = (const float*)d_in[1];
    const float* Whh = (const float*)d_in[2];
    const float* bih = (const float*)d_in[3];
    const float* bhh = (const float*)d_in[4];
    const float* fcw = (const float*)d_in[5];
    const float* fcb = (const float*)d_in[6];
    float* out = (float*)d_out;

    cudaFuncSetAttribute(xproj_kernel, cudaFuncAttributeMaxDynamicSharedMemorySize,
                         SMEM_XP_BYTES);
    cudaFuncSetAttribute(lstm_kernel, cudaFuncAttributeMaxDynamicSharedMemorySize,
                         SMEM_LSTM_BYTES);

    cvt_x_kernel<<<16384, 256>>>(x);
    cvt_w_kernel<<<512, 256>>>(Wih);
    xproj_kernel<<<dim3(16, 1024), 256, SMEM_XP_BYTES>>>(bih, bhh);
    lstm_kernel<<<NCTA, 256, SMEM_LSTM_BYTES>>>(Whh);
    fc_kernel<<<B_DIM, 320>>>(fcw, fcb, out);
}

// round 16
// speedup vs baseline: 1.6185x; 1.1831x over previous
#include <cuda_runtime.h>
#include <cuda_fp16.h>
#include <cstdint>
#include <math.h>

// Problem dims
#define B_DIM 128
#define S_DIM 1024
#define I_DIM 256
#define H_DIM 512
#define G4H   2048
#define O_DIM 10

// Recurrence partition: 128 persistent CTAs = 4 batch parts x 32 k parts
#define NCTA   128
#define PPARTS 4
#define QPARTS 32
#define GRP    32           // CTAs per barrier group (one batch part)
#define BP (B_DIM/PPARTS)   // 32 batch rows per CTA
#define KP (H_DIM/QPARTS)   // 16 h-columns per CTA

#define W2_PITCH 260        // 256 half2 + 4 pad -> conflict-free fragment LDS/LDSM
#define GS_PITCH 66

// smem: W slice [64][260] u32(half2) + h tile [32][260] u32 + gate slabs [4][32][66] f32
#define SMEM_LSTM_BYTES ((64*W2_PITCH + 32*W2_PITCH)*4 + 4*32*GS_PITCH*4)
// xproj: double-buffered A/B half tiles [2][128][36] u32 each
#define SMEM_XP_BYTES (4 * 128 * 36 * 4)

// Scratch (device globals: the sanctioned no-alloc workaround)
__device__ float g_xp[(size_t)S_DIM * B_DIM * G4H];        // 1 GB: x_proj [s][b][g]
__device__ __align__(256) __half g_x16[(size_t)B_DIM * S_DIM * I_DIM];  // fp16 x
__device__ __align__(256) __half g_w16[(size_t)G4H * I_DIM];            // fp16 W_ih
__device__ __align__(256) __half g_h[2][B_DIM * H_DIM];    // ping-pong h (fp16)
__device__ unsigned long long g_bar4[64];                  // 4 group barriers (monotonic)
__device__ uint32_t g_flag[PPARTS * QPARTS * 32];          // per-CTA step flags, 128B apart

__device__ __forceinline__ void cpa16(uint32_t smem_dst, const void* gsrc) {
    asm volatile("cp.async.cg.shared.global [%0], [%1], 16;\n"
                 :: "r"(smem_dst), "l"(gsrc));
}
__device__ __forceinline__ void cpa_commit() {
    asm volatile("cp.async.commit_group;\n" ::: "memory");
}
template <int N>
__device__ __forceinline__ void cpa_wait() {
    asm volatile("cp.async.wait_group %0;\n" :: "n"(N) : "memory");
}
__device__ __forceinline__ uint32_t ld_acq(const uint32_t* p) {
    uint32_t v;
    asm volatile("ld.acquire.gpu.global.b32 %0, [%1];" : "=r"(v) : "l"(p) : "memory");
    return v;
}
__device__ __forceinline__ void st_rel(uint32_t* p, uint32_t v) {
    asm volatile("st.release.gpu.global.b32 [%0], %1;" :: "l"(p), "r"(v) : "memory");
}
__device__ __forceinline__ void ldsm4(uint32_t& r0, uint32_t& r1, uint32_t& r2,
                                      uint32_t& r3, uint32_t a) {
    asm volatile("ldmatrix.sync.aligned.m8n8.x4.shared.b16 {%0,%1,%2,%3}, [%4];"
                 : "=r"(r0), "=r"(r1), "=r"(r2), "=r"(r3) : "r"(a));
}

// fp16 mma with fp32 accumulate
__device__ __forceinline__ void mma_f16(float& d0, float& d1, float& d2, float& d3,
                                        uint32_t a0, uint32_t a1, uint32_t a2, uint32_t a3,
                                        uint32_t b0, uint32_t b1) {
    asm volatile(
        "mma.sync.aligned.m16n8k16.row.col.f32.f16.f16.f32 "
        "{%0,%1,%2,%3},{%4,%5,%6,%7},{%8,%9},{%0,%1,%2,%3};"
        : "+f"(d0), "+f"(d1), "+f"(d2), "+f"(d3)
        : "r"(a0), "r"(a1), "r"(a2), "r"(a3), "r"(b0), "r"(b1));
}

// ============================================================================
// Phase 0: fp16 pre-conversion of x and W_ih (RNE).
// ============================================================================
__global__ __launch_bounds__(256) void cvt_x_kernel(const float* __restrict__ x) {
    size_t i = (size_t)blockIdx.x * 256 + threadIdx.x;
    const float4* src = reinterpret_cast<const float4*>(x) + i * 2;
    float4 v0 = src[0], v1 = src[1];
    __half2 h0 = __floats2half2_rn(v0.x, v0.y);
    __half2 h1 = __floats2half2_rn(v0.z, v0.w);
    __half2 h2 = __floats2half2_rn(v1.x, v1.y);
    __half2 h3 = __floats2half2_rn(v1.z, v1.w);
    uint4 o;
    o.x = *reinterpret_cast<uint32_t*>(&h0);
    o.y = *reinterpret_cast<uint32_t*>(&h1);
    o.z = *reinterpret_cast<uint32_t*>(&h2);
    o.w = *reinterpret_cast<uint32_t*>(&h3);
    reinterpret_cast<uint4*>(g_x16)[i] = o;
}

__global__ __launch_bounds__(256) void cvt_w_kernel(const float* __restrict__ Wih) {
    size_t i = (size_t)blockIdx.x * 256 + threadIdx.x;
    float4 v = reinterpret_cast<const float4*>(Wih)[i];
    __half2 h0 = __floats2half2_rn(v.x, v.y);
    __half2 h1 = __floats2half2_rn(v.z, v.w);
    uint2 o;
    o.x = *reinterpret_cast<uint32_t*>(&h0);
    o.y = *reinterpret_cast<uint32_t*>(&h1);
    reinterpret_cast<uint2*>(g_w16)[i] = o;
}

// ============================================================================
// Phase 1: x_proj = x @ W_ih^T + b_ih + b_hh. fp16 m16n8k16, fp32 accum.
// CTA: fixed s, M=128 batch, N=128 gate cols, K=256 halves in 4 chunks.
// ============================================================================
__global__ __launch_bounds__(256) void xproj_kernel(
    const float* __restrict__ bih, const float* __restrict__ bhh) {
    extern __shared__ uint32_t smx[];
    const int s   = blockIdx.y;
    const int n0  = blockIdx.x * 128;
    const int tid = threadIdx.x;
    const int warp = tid >> 5, lane = tid & 31;
    const int gid = lane >> 2, tq = lane & 3;
    const int mw = warp >> 1, nw = warp & 1;   // 4 M-warps x 2 N-warps

    const uint32_t smx_base = (uint32_t)__cvta_generic_to_shared(smx);

    auto load_chunk = [&](int kc4, int buf) {
        int kc = kc4 * 64;
#pragma unroll
        for (int j = 0; j < 4; j++) {
            int id = tid + 256 * j;            // 0..1023
            int r  = id >> 3;                  // row 0..127
            int c  = id & 7;                   // 8-half group
            cpa16(smx_base + (buf * 128 * 36 + r * 36 + c * 4) * 4,
                  g_x16 + ((size_t)r * S_DIM + s) * I_DIM + kc + c * 8);
            cpa16(smx_base + ((2 + buf) * 128 * 36 + r * 36 + c * 4) * 4,
                  g_w16 + (size_t)(n0 + r) * I_DIM + kc + c * 8);
        }
    };

    float acc[2][8][4] = {};

    load_chunk(0, 0);
    cpa_commit();

    for (int kc4 = 0; kc4 < 4; kc4++) {
        int cur = kc4 & 1;
        if (kc4 < 3) {
            load_chunk(kc4 + 1, cur ^ 1);
            cpa_commit();
            cpa_wait<1>();
        } else {
            cpa_wait<0>();
        }
        __syncthreads();

        const uint32_t* As = smx + cur * 128 * 36;
        const uint32_t* Bs = smx + (2 + cur) * 128 * 36;
#pragma unroll
        for (int ks = 0; ks < 4; ks++) {        // 4 k16 steps per chunk
            int k2 = ks * 8;                    // half2 base
            uint32_t a[2][4];
#pragma unroll
            for (int mt = 0; mt < 2; mt++) {
                int m0 = mw * 32 + mt * 16;
                a[mt][0] = As[(m0 + gid) * 36 + k2 + tq];
                a[mt][1] = As[(m0 + gid + 8) * 36 + k2 + tq];
                a[mt][2] = As[(m0 + gid) * 36 + k2 + tq + 4];
                a[mt][3] = As[(m0 + gid + 8) * 36 + k2 + tq + 4];
            }
#pragma unroll
            for (int nt = 0; nt < 8; nt++) {
                int nn = nw * 64 + nt * 8;
                uint32_t b0 = Bs[(nn + gid) * 36 + k2 + tq];
                uint32_t b1 = Bs[(nn + gid) * 36 + k2 + tq + 4];
                mma_f16(acc[0][nt][0], acc[0][nt][1], acc[0][nt][2], acc[0][nt][3],
                        a[0][0], a[0][1], a[0][2], a[0][3], b0, b1);
                mma_f16(acc[1][nt][0], acc[1][nt][1], acc[1][nt][2], acc[1][nt][3],
                        a[1][0], a[1][1], a[1][2], a[1][3], b0, b1);
            }
        }
        __syncthreads();
    }

#pragma unroll
    for (int mt = 0; mt < 2; mt++) {
        int row = mw * 32 + mt * 16 + gid;       // batch row
#pragma unroll
        for (int nt = 0; nt < 8; nt++) {
            int col = n0 + nw * 64 + nt * 8 + tq * 2;
            float bs0 = bih[col]     + bhh[col];
            float bs1 = bih[col + 1] + bhh[col + 1];
            size_t r0 = ((size_t)s * B_DIM + row) * G4H + col;
            size_t r1 = ((size_t)s * B_DIM + row + 8) * G4H + col;
            g_xp[r0]     = acc[mt][nt][0] + bs0;
            g_xp[r0 + 1] = acc[mt][nt][1] + bs1;
            g_xp[r1]     = acc[mt][nt][2] + bs0;
            g_xp[r1 + 1] = acc[mt][nt][3] + bs1;
        }
    }
}

// ============================================================================
// Phase 2: persistent recurrence, fp16 m16n8k16 / fp32 accum.
// Per-CTA step flags (release/acquire), ldmatrix fragment loads,
// 2-sub-chunk cp.async pipeline overlapping L2 latency with MMA.
// ============================================================================
__global__ __launch_bounds__(256, 1) void lstm_kernel(const float* __restrict__ Whh) {
    extern __shared__ uint32_t sm[];
    uint32_t* Ws = sm;                                   // [64][260] half2
    uint32_t* hs = sm + 64 * W2_PITCH;                   // [32][260] half2
    float*    gs = (float*)(sm + (64 + 32) * W2_PITCH);  // [4][32][66]

    const int tid  = threadIdx.x;
    const int warp = tid >> 5, lane = tid & 31;
    const int gid  = lane >> 2, tq = lane & 3;
    const int kp = warp & 3;         // k-part: K range [kp*128, kp*128+128)
    const int nh = warp >> 2;        // n-half: N cols [nh*32, nh*32+32)
    const int pl = nh * 32 + lane;   // lane id within the kp warp pair (0..63)
    const int q = blockIdx.x & (QPARTS - 1);
    const int p = blockIdx.x >> 5;

    const uint32_t hs_base = (uint32_t)__cvta_generic_to_shared(hs);
    const uint32_t ws_base = (uint32_t)__cvta_generic_to_shared(Ws);
    uint32_t* myflag = &g_flag[(p * QPARTS + q) * 32];
    const uint32_t* prodflag = &g_flag[(p * QPARTS + kp * 8 + (lane & 7)) * 32];

    // ldmatrix lane address offsets (u32 units, W2_PITCH rows), k-base added per step.
    // A tiles (mt=0/1): rows mt*16 + (lane&15), +8-half col offset for lanes>=16.
    const uint32_t a_off0 = (uint32_t)(((lane & 15)) * W2_PITCH + ((lane >> 4) << 2));
    const uint32_t a_off1 = a_off0 + 16u * W2_PITCH;
    // B tiles (nt2=0/1): rows nh*32 + nt2*16 + (lane&7) + ((lane>>4)<<3),
    // +8-half col offset when bit3 of lane set.
    const uint32_t b_row = (uint32_t)(nh * 32 + (lane & 7) + ((lane >> 4) << 3));
    const uint32_t b_off0 = b_row * W2_PITCH + (((lane >> 3) & 1) << 2);
    const uint32_t b_off1 = b_off0 + 16u * W2_PITCH;

    // Reset own flag for this launch (replay safety).
    if (tid == 0) *myflag = 0;

    // Load resident W_hh slice as half2 (RNE). Row r (0..63): gate r/16, k-col q*16 + r%16.
#pragma unroll
    for (int it = 0; it < 64; it++) {
        int id = tid + 256 * it;           // 0..16383
        int r  = id >> 8;                  // 0..63
        int c2 = id & 255;                 // half2 index 0..255
        int grow = (r >> 4) * H_DIM + q * KP + (r & 15);
        float f0 = Whh[(size_t)grow * H_DIM + 2 * c2];
        float f1 = Whh[(size_t)grow * H_DIM + 2 * c2 + 1];
        __half2 hv = __floats2half2_rn(f0, f1);
        Ws[r * W2_PITCH + c2] = *reinterpret_cast<uint32_t*>(&hv);
    }

    // One group barrier: all 32 CTAs' flag resets visible before any polling.
    __syncthreads();
    if (tid == 0) {
        __threadfence();
        unsigned long long* bar = &g_bar4[p * 16];
        unsigned long long ticket = atomicAdd(bar, 1ULL);
        unsigned long long target = (ticket / GRP + 1) * (unsigned long long)GRP;
        while (*(volatile unsigned long long*)bar < target) { }
        __threadfence();
    }
    __syncthreads();

    // Persistent c-state: thread owns (b,k) pairs tid and tid+256.
    float creg[2] = {0.f, 0.f};
    const int kk = tid & 15;

    // Prefetch x_proj gate values for t=0.
    float xv[2][4];
    {
        const float* xps = g_xp + ((size_t)p * BP) * G4H;
#pragma unroll
        for (int r2 = 0; r2 < 2; r2++) {
            int bl = (tid + r2 * 256) >> 4;
#pragma unroll
            for (int g = 0; g < 4; g++)
                xv[r2][g] = xps[(size_t)bl * G4H + g * 512 + q * KP + kk];
        }
    }

    for (int t = 0; t < S_DIM; t++) {
        float acc[2][4][4] = {};
        if (t > 0) {
            // Wait for our 8 producers to have published h_{t-1} (flag >= t).
            if (lane < 8) {
                while (ld_acq(prodflag) < (uint32_t)t) { }
            }
            asm volatile("bar.sync %0, 64;" :: "r"(1 + kp) : "memory");

            // Stage the pair's 8KB fp16 h chunk as two 4KB cp.async groups.
            const __half* hp = g_h[(t + 1) & 1] + (size_t)p * BP * H_DIM;
#pragma unroll
            for (int sub = 0; sub < 2; sub++) {
#pragma unroll
                for (int j = 0; j < 4; j++) {
                    int id = pl + 64 * j;          // 0..255
                    int r  = id >> 3;              // 0..31
                    int c8 = (id & 7) * 8;         // half offset within sub-chunk
                    cpa16(hs_base + (r * W2_PITCH + kp * 64 + sub * 32 + (c8 >> 1)) * 4,
                          hp + (size_t)r * H_DIM + kp * 128 + sub * 64 + c8);
                }
                cpa_commit();
            }

#pragma unroll
            for (int sub = 0; sub < 2; sub++) {
                if (sub == 0) { cpa_wait<1>(); } else { cpa_wait<0>(); }
                asm volatile("bar.sync %0, 64;" :: "r"(1 + kp) : "memory");
#pragma unroll
                for (int ks = 0; ks < 4; ks++) {
                    uint32_t k0u = (uint32_t)(kp * 64 + sub * 32 + ks * 8);
                    uint32_t a0[4], a1[4], bb0[4], bb1[4];
                    ldsm4(a0[0], a0[1], a0[2], a0[3],
                          hs_base + (a_off0 + k0u) * 4);
                    ldsm4(a1[0], a1[1], a1[2], a1[3],
                          hs_base + (a_off1 + k0u) * 4);
                    ldsm4(bb0[0], bb0[1], bb0[2], bb0[3],
                          ws_base + (b_off0 + k0u) * 4);
                    ldsm4(bb1[0], bb1[1], bb1[2], bb1[3],
                          ws_base + (b_off1 + k0u) * 4);
                    // nt 0,1 from bb0; nt 2,3 from bb1
                    mma_f16(acc[0][0][0], acc[0][0][1], acc[0][0][2], acc[0][0][3],
                            a0[0], a0[1], a0[2], a0[3], bb0[0], bb0[1]);
                    mma_f16(acc[1][0][0], acc[1][0][1], acc[1][0][2], acc[1][0][3],
                            a1[0], a1[1], a1[2], a1[3], bb0[0], bb0[1]);
                    mma_f16(acc[0][1][0], acc[0][1][1], acc[0][1][2], acc[0][1][3],
                            a0[0], a0[1], a0[2], a0[3], bb0[2], bb0[3]);
                    mma_f16(acc[1][1][0], acc[1][1][1], acc[1][1][2], acc[1][1][3],
                            a1[0], a1[1], a1[2], a1[3], bb0[2], bb0[3]);
                    mma_f16(acc[0][2][0], acc[0][2][1], acc[0][2][2], acc[0][2][3],
                            a0[0], a0[1], a0[2], a0[3], bb1[0], bb1[1]);
                    mma_f16(acc[1][2][0], acc[1][2][1], acc[1][2][2], acc[1][2][3],
                            a1[0], a1[1], a1[2], a1[3], bb1[0], bb1[1]);
                    mma_f16(acc[0][3][0], acc[0][3][1], acc[0][3][2], acc[0][3][3],
                            a0[0], a0[1], a0[2], a0[3], bb1[2], bb1[3]);
                    mma_f16(acc[1][3][0], acc[1][3][1], acc[1][3][2], acc[1][3][3],
                            a1[0], a1[1], a1[2], a1[3], bb1[2], bb1[3]);
                }
            }
        }

        // Scatter k-part partials into slab kp (float2 stores).
        {
            float* gsp = gs + kp * 32 * GS_PITCH;
#pragma unroll
            for (int mt = 0; mt < 2; mt++) {
                int row = mt * 16 + gid;
#pragma unroll
                for (int nt = 0; nt < 4; nt++) {
                    int col = nh * 32 + nt * 8 + tq * 2;
                    *reinterpret_cast<float2*>(gsp + row * GS_PITCH + col) =
                        make_float2(acc[mt][nt][0], acc[mt][nt][1]);
                    *reinterpret_cast<float2*>(gsp + (row + 8) * GS_PITCH + col) =
                        make_float2(acc[mt][nt][2], acc[mt][nt][3]);
                }
            }
        }

        // Prefetch next step's x_proj early: DRAM latency overlaps the
        // elementwise stage + publish + next poll. Separate buffer (xvn).
        float xvn[2][4];
        if (t + 1 < S_DIM) {
            const float* xps = g_xp + ((size_t)(t + 1) * B_DIM + p * BP) * G4H;
#pragma unroll
            for (int r2 = 0; r2 < 2; r2++) {
                int bl = (tid + r2 * 256) >> 4;
#pragma unroll
                for (int g = 0; g < 4; g++)
                    xvn[r2][g] = xps[(size_t)bl * G4H + g * 512 + q * KP + kk];
            }
        }
        __syncthreads();

        // Elementwise: sum 4 k-slabs + x_proj, gate math, c update, h write (fp16 RNE).
        __half* hdst = g_h[t & 1];
#pragma unroll
        for (int r2 = 0; r2 < 2; r2++) {
            int bl = (tid + r2 * 256) >> 4;
            float yi = xv[r2][0], yf = xv[r2][1], yg = xv[r2][2], yo = xv[r2][3];
#pragma unroll
            for (int s4 = 0; s4 < 4; s4++) {
                const float* gb = gs + (s4 * 32 + bl) * GS_PITCH;
                yi += gb[kk];
                yf += gb[16 + kk];
                yg += gb[32 + kk];
                yo += gb[48 + kk];
            }
            float ig = 1.f / (1.f + expf(-yi));
            float fg = 1.f / (1.f + expf(-yf));
            float gg = fmaxf(yg, 0.f);
            float og = 1.f / (1.f + expf(-yo));
            creg[r2] = fg * creg[r2] + ig * gg;
            hdst[(size_t)(p * BP + bl) * H_DIM + q * KP + kk] = __float2half_rn(og * creg[r2]);
        }
#pragma unroll
        for (int r2 = 0; r2 < 2; r2++)
#pragma unroll
            for (int g = 0; g < 4; g++) xv[r2][g] = xvn[r2][g];

        // bar gives intra-CTA happens-before for all h stores; tid0's release
        // store extends it cross-CTA (cooperative-groups barrier pattern).
        __syncthreads();
        if (tid == 0) st_rel(myflag, (uint32_t)(t + 1));
    }
}

// ============================================================================
// Phase 3: out[b][o] = h_final[b] . fc_w[o] + fc_b[o]; h_final = g_h[1].
// ============================================================================
__global__ __launch_bounds__(320) void fc_kernel(const float* __restrict__ fcw,
                                                 const float* __restrict__ fcb,
                                                 float* __restrict__ out) {
    int b = blockIdx.x;
    int w = threadIdx.x >> 5, lane = threadIdx.x & 31;
    const __half* h = g_h[1] + (size_t)b * H_DIM;
    float s = 0.f;
    for (int k = lane; k < H_DIM; k += 32) s += __half2float(h[k]) * fcw[w * H_DIM + k];
#pragma unroll
    for (int off = 16; off; off >>= 1) s += __shfl_down_sync(0xffffffffu, s, off);
    if (lane == 0) out[b * O_DIM + w] = s + fcb[w];
}

extern "C" void kernel_launch(void* const* d_in, const int* in_sizes, int n_in,
                              void* d_out, int out_size) {
    const float* x   = (const float*)d_in[0];
    const float* Wih = (const float*)d_in[1];
    const float* Whh = (const float*)d_in[2];
    const float* bih = (const float*)d_in[3];
    const float* bhh = (const float*)d_in[4];
    const float* fcw = (const float*)d_in[5];
    const float* fcb = (const float*)d_in[6];
    float* out = (float*)d_out;

    cudaFuncSetAttribute(xproj_kernel, cudaFuncAttributeMaxDynamicSharedMemorySize,
                         SMEM_XP_BYTES);
    cudaFuncSetAttribute(lstm_kernel, cudaFuncAttributeMaxDynamicSharedMemorySize,
                         SMEM_LSTM_BYTES);

    cvt_x_kernel<<<16384, 256>>>(x);
    cvt_w_kernel<<<512, 256>>>(Wih);
    xproj_kernel<<<dim3(16, 1024), 256, SMEM_XP_BYTES>>>(bih, bhh);
    lstm_kernel<<<NCTA, 256, SMEM_LSTM_BYTES>>>(Whh);
    fc_kernel<<<B_DIM, 320>>>(fcw, fcb, out);
}